// round 10
// baseline (speedup 1.0000x reference)
#include <cuda_runtime.h>
#include <math.h>

// Problem constants
#define TT 26
#define NB 2
#define NT (NB*TT)      // 52 frames
#define CC 256
#define HW 256          // 16*16
#define NHEAD 8
#define CPH 32          // C / NHEAD

// ---------------------------------------------------------------------------
// init_out: out[n][oc][hw] = b_out[oc]  (also clears the 0xAA poison)
// ---------------------------------------------------------------------------
__global__ __launch_bounds__(256, 1)
void init_out(const float* __restrict__ b_out, float* __restrict__ out, int total)
{
    int i = blockIdx.x * blockDim.x + threadIdx.x;
    if (i < total) out[i] = b_out[(i >> 8) & 255];
}

// ---------------------------------------------------------------------------
// Fused attention + output projection. One block per (frame n, head).
// 512 threads = 2 threads per query (each owns 16 of 32 channels).
//
//  Phase A: q[16] per thread, recomputed from x and w_qkv (chunked weights).
//  Per gathered half-tile (4 frames x 2 halves of 128 keys):
//    build K/V tile (128 x 32) in smem from x and w_qkv (chunked weights),
//    then exact online softmax accumulation into acc[16].
//  Epilogue: out[n][oc][hw] += sum_c o[c]*w_out[oc][c], via one atomicAdd
//    per (oc, hw) from the even lane of each query pair.
//
// No local arrays with runtime indices, no vector-struct locals, no fp16:
// zero local-memory frame by construction.
// ---------------------------------------------------------------------------
__global__ __launch_bounds__(512, 1)
void attn_fused(const float* __restrict__ x,
                const float* __restrict__ w_qkv,
                const float* __restrict__ b_qkv,
                const float* __restrict__ w_out,
                const int* __restrict__ access,
                float* __restrict__ out)
{
    // Layout (floats):
    //   Ks [128][33]  @ 0      (4224)   } padded rows: conflict-free build
    //   Vs [128][33]  @ 4224   (4224)
    //   Wk [32][32]   @ 8448   (1024)   } weight chunk staging (also WqT)
    //   Wv [32][32]   @ 9472   (1024)
    //   Epilogue overlays woT[256][32] (8192) @ 0.
    __shared__ float sm[10496];
    float* Ks = sm;
    float* Vs = sm + 4224;
    float* Wk = sm + 8448;
    float* Wv = sm + 9472;

    const int tid   = threadIdx.x;
    const int query = tid >> 1;           // 0..255 (= hw)
    const int half  = tid & 1;
    const int qoff  = half * 16;          // my channel group within the head
    const int bid   = blockIdx.x;
    const int n     = bid >> 3;           // global frame
    const int head  = bid & 7;
    const int t     = n % TT;
    const int b_    = n / TT;

    // ---- Phase A: recompute q[16] (chunked Wq staging through Wk region) ----
    float q0=0.f,q1=0.f,q2=0.f,q3=0.f,q4=0.f,q5=0.f,q6=0.f,q7=0.f;
    float q8=0.f,q9=0.f,q10=0.f,q11=0.f,q12=0.f,q13=0.f,q14=0.f,q15=0.f;

    const float* xq = x + (size_t)n * (CC * HW) + query;
    for (int c0 = 0; c0 < 256; c0 += 32) {
        __syncthreads();
        {
            int idx = tid;                 // 0..511
            int ch = idx & 31, cc = idx >> 5;
            Wk[ch * 32 + cc] = w_qkv[(size_t)(cc * 8 + head) * CC + c0 + ch];
            idx = tid + 512;               // 512..1023
            ch = idx & 31; cc = idx >> 5;
            Wk[ch * 32 + cc] = w_qkv[(size_t)(cc * 8 + head) * CC + c0 + ch];
        }
        __syncthreads();
#pragma unroll 8
        for (int ch = 0; ch < 32; ch++) {
            float xv = xq[(size_t)(c0 + ch) * HW];
            const float* wr = Wk + ch * 32 + qoff;
            q0  = fmaf(xv, wr[0],  q0);  q1  = fmaf(xv, wr[1],  q1);
            q2  = fmaf(xv, wr[2],  q2);  q3  = fmaf(xv, wr[3],  q3);
            q4  = fmaf(xv, wr[4],  q4);  q5  = fmaf(xv, wr[5],  q5);
            q6  = fmaf(xv, wr[6],  q6);  q7  = fmaf(xv, wr[7],  q7);
            q8  = fmaf(xv, wr[8],  q8);  q9  = fmaf(xv, wr[9],  q9);
            q10 = fmaf(xv, wr[10], q10); q11 = fmaf(xv, wr[11], q11);
            q12 = fmaf(xv, wr[12], q12); q13 = fmaf(xv, wr[13], q13);
            q14 = fmaf(xv, wr[14], q14); q15 = fmaf(xv, wr[15], q15);
        }
    }
    const float scale = 0.17677669529663687f;   // 1/sqrt(32)
    q0  = (q0  + b_qkv[(qoff+0)*8+head])  * scale;
    q1  = (q1  + b_qkv[(qoff+1)*8+head])  * scale;
    q2  = (q2  + b_qkv[(qoff+2)*8+head])  * scale;
    q3  = (q3  + b_qkv[(qoff+3)*8+head])  * scale;
    q4  = (q4  + b_qkv[(qoff+4)*8+head])  * scale;
    q5  = (q5  + b_qkv[(qoff+5)*8+head])  * scale;
    q6  = (q6  + b_qkv[(qoff+6)*8+head])  * scale;
    q7  = (q7  + b_qkv[(qoff+7)*8+head])  * scale;
    q8  = (q8  + b_qkv[(qoff+8)*8+head])  * scale;
    q9  = (q9  + b_qkv[(qoff+9)*8+head])  * scale;
    q10 = (q10 + b_qkv[(qoff+10)*8+head]) * scale;
    q11 = (q11 + b_qkv[(qoff+11)*8+head]) * scale;
    q12 = (q12 + b_qkv[(qoff+12)*8+head]) * scale;
    q13 = (q13 + b_qkv[(qoff+13)*8+head]) * scale;
    q14 = (q14 + b_qkv[(qoff+14)*8+head]) * scale;
    q15 = (q15 + b_qkv[(qoff+15)*8+head]) * scale;

    // ---- Online softmax over 4 gathered frames x 2 half-tiles of 128 keys ----
    float mx = -1e30f, l = 0.f;
    float a0=0.f,a1=0.f,a2=0.f,a3=0.f,a4=0.f,a5=0.f,a6=0.f,a7=0.f;
    float a8=0.f,a9=0.f,a10=0.f,a11=0.f,a12=0.f,a13=0.f,a14=0.f,a15=0.f;

    const int kk   = tid >> 2;            // key 0..127 (build mapping)
    const int coff = (tid & 3) * 8;       // channel group 0,8,16,24

    for (int tt = 0; tt < 8; tt++) {
        const int g  = tt >> 1;
        const int hf = tt & 1;
        const int f  = access[t * 4 + g];
        const int nf = b_ * TT + f;
        const float* xk = x + (size_t)nf * (CC * HW) + hf * 128 + kk;

        // -- build K/V tile: each thread accumulates 8 K-cols and 8 V-cols --
        float k0=0.f,k1=0.f,k2=0.f,k3=0.f,k4=0.f,k5=0.f,k6=0.f,k7=0.f;
        float v0=0.f,v1=0.f,v2=0.f,v3=0.f,v4=0.f,v5=0.f,v6=0.f,v7=0.f;
        for (int c0 = 0; c0 < 256; c0 += 32) {
            __syncthreads();
            {
                int idx = tid;
                int ch = idx & 31, cc = idx >> 5;
                Wk[ch*32+cc] = w_qkv[(size_t)(256 + cc*8 + head) * CC + c0 + ch];
                Wv[ch*32+cc] = w_qkv[(size_t)(512 + cc*8 + head) * CC + c0 + ch];
                idx = tid + 512;
                ch = idx & 31; cc = idx >> 5;
                Wk[ch*32+cc] = w_qkv[(size_t)(256 + cc*8 + head) * CC + c0 + ch];
                Wv[ch*32+cc] = w_qkv[(size_t)(512 + cc*8 + head) * CC + c0 + ch];
            }
            __syncthreads();
#pragma unroll 4
            for (int ch = 0; ch < 32; ch++) {
                float xv = xk[(size_t)(c0 + ch) * HW];
                const float* wkr = Wk + ch * 32 + coff;
                const float* wvr = Wv + ch * 32 + coff;
                k0 = fmaf(xv, wkr[0], k0); k1 = fmaf(xv, wkr[1], k1);
                k2 = fmaf(xv, wkr[2], k2); k3 = fmaf(xv, wkr[3], k3);
                k4 = fmaf(xv, wkr[4], k4); k5 = fmaf(xv, wkr[5], k5);
                k6 = fmaf(xv, wkr[6], k6); k7 = fmaf(xv, wkr[7], k7);
                v0 = fmaf(xv, wvr[0], v0); v1 = fmaf(xv, wvr[1], v1);
                v2 = fmaf(xv, wvr[2], v2); v3 = fmaf(xv, wvr[3], v3);
                v4 = fmaf(xv, wvr[4], v4); v5 = fmaf(xv, wvr[5], v5);
                v6 = fmaf(xv, wvr[6], v6); v7 = fmaf(xv, wvr[7], v7);
            }
        }
        {
            float* kd = Ks + kk * 33 + coff;
            kd[0] = k0 + b_qkv[256 + (coff+0)*8 + head];
            kd[1] = k1 + b_qkv[256 + (coff+1)*8 + head];
            kd[2] = k2 + b_qkv[256 + (coff+2)*8 + head];
            kd[3] = k3 + b_qkv[256 + (coff+3)*8 + head];
            kd[4] = k4 + b_qkv[256 + (coff+4)*8 + head];
            kd[5] = k5 + b_qkv[256 + (coff+5)*8 + head];
            kd[6] = k6 + b_qkv[256 + (coff+6)*8 + head];
            kd[7] = k7 + b_qkv[256 + (coff+7)*8 + head];
            float* vd = Vs + kk * 33 + coff;
            vd[0] = v0 + b_qkv[512 + (coff+0)*8 + head];
            vd[1] = v1 + b_qkv[512 + (coff+1)*8 + head];
            vd[2] = v2 + b_qkv[512 + (coff+2)*8 + head];
            vd[3] = v3 + b_qkv[512 + (coff+3)*8 + head];
            vd[4] = v4 + b_qkv[512 + (coff+4)*8 + head];
            vd[5] = v5 + b_qkv[512 + (coff+5)*8 + head];
            vd[6] = v6 + b_qkv[512 + (coff+6)*8 + head];
            vd[7] = v7 + b_qkv[512 + (coff+7)*8 + head];
        }
        __syncthreads();

        // -- consume 128 keys --
        for (int j = 0; j < 128; j++) {
            const float* kr = Ks + j * 33 + qoff;
            float sp = 0.f;
            sp = fmaf(q0,  kr[0],  sp); sp = fmaf(q1,  kr[1],  sp);
            sp = fmaf(q2,  kr[2],  sp); sp = fmaf(q3,  kr[3],  sp);
            sp = fmaf(q4,  kr[4],  sp); sp = fmaf(q5,  kr[5],  sp);
            sp = fmaf(q6,  kr[6],  sp); sp = fmaf(q7,  kr[7],  sp);
            sp = fmaf(q8,  kr[8],  sp); sp = fmaf(q9,  kr[9],  sp);
            sp = fmaf(q10, kr[10], sp); sp = fmaf(q11, kr[11], sp);
            sp = fmaf(q12, kr[12], sp); sp = fmaf(q13, kr[13], sp);
            sp = fmaf(q14, kr[14], sp); sp = fmaf(q15, kr[15], sp);
            float s = sp + __shfl_xor_sync(0xFFFFFFFFu, sp, 1);
            if (s > mx) {                          // rare rescale
                float corr = __expf(mx - s);
                l *= corr;
                a0*=corr; a1*=corr; a2*=corr; a3*=corr;
                a4*=corr; a5*=corr; a6*=corr; a7*=corr;
                a8*=corr; a9*=corr; a10*=corr; a11*=corr;
                a12*=corr; a13*=corr; a14*=corr; a15*=corr;
                mx = s;
            }
            float p = __expf(s - mx);
            l += p;
            const float* vr = Vs + j * 33 + qoff;
            a0  = fmaf(p, vr[0],  a0);  a1  = fmaf(p, vr[1],  a1);
            a2  = fmaf(p, vr[2],  a2);  a3  = fmaf(p, vr[3],  a3);
            a4  = fmaf(p, vr[4],  a4);  a5  = fmaf(p, vr[5],  a5);
            a6  = fmaf(p, vr[6],  a6);  a7  = fmaf(p, vr[7],  a7);
            a8  = fmaf(p, vr[8],  a8);  a9  = fmaf(p, vr[9],  a9);
            a10 = fmaf(p, vr[10], a10); a11 = fmaf(p, vr[11], a11);
            a12 = fmaf(p, vr[12], a12); a13 = fmaf(p, vr[13], a13);
            a14 = fmaf(p, vr[14], a14); a15 = fmaf(p, vr[15], a15);
        }
        __syncthreads();    // Ks/Vs reads done before next tile's writes
    }

    // normalize o
    {
        float inv = 1.f / l;
        a0*=inv; a1*=inv; a2*=inv; a3*=inv; a4*=inv; a5*=inv; a6*=inv; a7*=inv;
        a8*=inv; a9*=inv; a10*=inv; a11*=inv; a12*=inv; a13*=inv; a14*=inv; a15*=inv;
    }

    // ---- Epilogue: fused output projection, atomicAdd into out ----
    // stage woT[oc][c] = w_out[oc][c*8+head] over the (dead) Ks/Vs region
    __syncthreads();
#pragma unroll
    for (int r = 0; r < 16; r++) {
        int idx = tid + r * 512;          // 0..8191
        int oc = idx >> 5, cc = idx & 31;
        sm[oc * 32 + cc] = w_out[(size_t)oc * CC + cc * 8 + head];
    }
    __syncthreads();

    float* ob = out + (size_t)n * (CC * HW) + query;
    for (int oc = 0; oc < 256; oc++) {
        const float* wr = sm + oc * 32 + qoff;
        float sp = 0.f;
        sp = fmaf(a0,  wr[0],  sp); sp = fmaf(a1,  wr[1],  sp);
        sp = fmaf(a2,  wr[2],  sp); sp = fmaf(a3,  wr[3],  sp);
        sp = fmaf(a4,  wr[4],  sp); sp = fmaf(a5,  wr[5],  sp);
        sp = fmaf(a6,  wr[6],  sp); sp = fmaf(a7,  wr[7],  sp);
        sp = fmaf(a8,  wr[8],  sp); sp = fmaf(a9,  wr[9],  sp);
        sp = fmaf(a10, wr[10], sp); sp = fmaf(a11, wr[11], sp);
        sp = fmaf(a12, wr[12], sp); sp = fmaf(a13, wr[13], sp);
        sp = fmaf(a14, wr[14], sp); sp = fmaf(a15, wr[15], sp);
        sp += __shfl_xor_sync(0xFFFFFFFFu, sp, 1);
        if (half == 0)
            atomicAdd(ob + (size_t)oc * HW, sp);
    }
}

// ---------------------------------------------------------------------------
extern "C" void kernel_launch(void* const* d_in, const int* in_sizes, int n_in,
                              void* d_out, int out_size)
{
    const float* x      = (const float*)d_in[0];
    const float* w_qkv  = (const float*)d_in[1];
    const float* b_qkv  = (const float*)d_in[2];
    const float* w_out  = (const float*)d_in[3];
    const float* b_out  = (const float*)d_in[4];
    const int*   access = (const int*)d_in[5];
    float* out = (float*)d_out;

    const int total = NT * CC * HW;                    // 3,407,872
    init_out<<<(total + 255) / 256, 256>>>(b_out, out, total);
    attn_fused<<<NT * NHEAD, 512>>>(x, w_qkv, b_qkv, w_out, access, out);
}